// round 4
// baseline (speedup 1.0000x reference)
#include <cuda_runtime.h>
#include <cstdint>

#define T_STEPS 2048
#define BATCH   64
#define IDIM    512
#define HDIM    512

#define N_GROUPS 8
#define BLKS_PER_GROUP 16
#define B_PER_GROUP 8
#define COLS_PER_BLK 32

typedef unsigned long long u64;

// ---------------- scratch (static device allocations) ----------------------
__device__ float g_xf[(long)T_STEPS * BATCH * HDIM];
__device__ float g_xh[(long)T_STEPS * BATCH * HDIM];
__device__ float g_hbuf[BATCH * HDIM];
__device__ float g_gbuf[BATCH * HDIM];
__device__ unsigned int g_cnt[N_GROUPS * 32];   // 4 counters/group, 32B apart

// ---------------- packed f32x2 helpers --------------------------------------
__device__ __forceinline__ u64 pack2(float x, float y) {
    u64 r; asm("mov.b64 %0, {%1, %2};" : "=l"(r) : "f"(x), "f"(y)); return r;
}
__device__ __forceinline__ u64 ffma2(u64 a, u64 b, u64 c) {
    u64 d; asm("fma.rn.f32x2 %0, %1, %2, %3;" : "=l"(d) : "l"(a), "l"(b), "l"(c));
    return d;
}
__device__ __forceinline__ float2 unpack2(u64 a) {
    float2 r; asm("mov.b64 {%0, %1}, %2;" : "=f"(r.x), "=f"(r.y) : "l"(a)); return r;
}
__device__ __forceinline__ float4 ldcg4(const float4* p) {
    float4 v;
    asm volatile("ld.global.cg.v4.f32 {%0,%1,%2,%3}, [%4];"
                 : "=f"(v.x), "=f"(v.y), "=f"(v.z), "=f"(v.w) : "l"(p));
    return v;
}
__device__ __forceinline__ void red_release(unsigned int* p) {
    asm volatile("red.release.gpu.global.add.u32 [%0], 1;" :: "l"(p) : "memory");
}
__device__ __forceinline__ unsigned int ld_acq(const unsigned int* p) {
    unsigned int v;
    asm volatile("ld.acquire.gpu.global.u32 %0, [%1];" : "=r"(v) : "l"(p) : "memory");
    return v;
}

// ---------------- cluster / mbarrier helpers --------------------------------
__device__ __forceinline__ uint32_t smem_u32(const void* p) {
    return (uint32_t)__cvta_generic_to_shared(p);
}
__device__ __forceinline__ void mbar_init(uint32_t a, uint32_t cnt) {
    asm volatile("mbarrier.init.shared.b64 [%0], %1;" :: "r"(a), "r"(cnt) : "memory");
}
__device__ __forceinline__ void arrive_all16(uint32_t a) {
    #pragma unroll
    for (int r = 0; r < 16; r++) {
        uint32_t ra;
        asm("mapa.shared::cluster.u32 %0, %1, %2;" : "=r"(ra) : "r"(a), "r"(r));
        asm volatile("mbarrier.arrive.release.cluster.shared::cluster.b64 _, [%0];"
                     :: "r"(ra) : "memory");
    }
}
__device__ __forceinline__ void mbar_wait(uint32_t a, uint32_t par) {
    asm volatile(
        "{\n\t.reg .pred P;\n"
        "W%=:\n\t"
        "mbarrier.try_wait.parity.acquire.cluster.shared::cta.b64 P, [%0], %1;\n\t"
        "@P bra D%=;\n\t"
        "bra W%=;\n"
        "D%=:\n\t}"
        :: "r"(a), "r"(par) : "memory");
}
__device__ __forceinline__ void push16(uint32_t a, float v) {
    #pragma unroll
    for (int r = 0; r < 16; r++) {
        uint32_t ra;
        asm("mapa.shared::cluster.u32 %0, %1, %2;" : "=r"(ra) : "r"(a), "r"(r));
        asm volatile("st.shared::cluster.f32 [%0], %1;" :: "r"(ra), "f"(v) : "memory");
    }
}
#define CLUSTER_SYNC() do { \
    asm volatile("barrier.cluster.arrive.aligned;" ::: "memory"); \
    asm volatile("barrier.cluster.wait.aligned;" ::: "memory"); } while (0)

__device__ __forceinline__ float sigmoid_f(float x) {
    return 1.0f / (1.0f + __expf(-x));
}
__device__ __forceinline__ float tanh_f(float x) {
    return 1.0f - 2.0f / (__expf(2.0f * x) + 1.0f);
}

// 4-row GEMM half-phase: acc[b] += sum_k w[j][k] * src[b][k] over this
// thread's 64-k slice; weights register-resident (pre-packed u64).
__device__ __forceinline__ void gemm4(const u64* __restrict__ w2,
                                      const float* __restrict__ src,
                                      int kb, float* __restrict__ part,
                                      int ks, int j)
{
    u64 a0 = 0ull, a1 = 0ull, a2 = 0ull, a3 = 0ull;
    #pragma unroll
    for (int i = 0; i < 16; i++) {
        u64 wlo = w2[2 * i], whi = w2[2 * i + 1];
        float4 x0 = *(const float4*)&src[0 * 512 + kb + 4 * i];
        float4 x1 = *(const float4*)&src[1 * 512 + kb + 4 * i];
        float4 x2 = *(const float4*)&src[2 * 512 + kb + 4 * i];
        float4 x3 = *(const float4*)&src[3 * 512 + kb + 4 * i];
        a0 = ffma2(wlo, pack2(x0.x, x0.y), a0);
        a0 = ffma2(whi, pack2(x0.z, x0.w), a0);
        a1 = ffma2(wlo, pack2(x1.x, x1.y), a1);
        a1 = ffma2(whi, pack2(x1.z, x1.w), a1);
        a2 = ffma2(wlo, pack2(x2.x, x2.y), a2);
        a2 = ffma2(whi, pack2(x2.z, x2.w), a2);
        a3 = ffma2(wlo, pack2(x3.x, x3.y), a3);
        a3 = ffma2(whi, pack2(x3.z, x3.w), a3);
    }
    float2 r0 = unpack2(a0), r1 = unpack2(a1), r2 = unpack2(a2), r3 = unpack2(a3);
    part[(0 * 8 + ks) * 32 + j] = r0.x + r0.y;
    part[(1 * 8 + ks) * 32 + j] = r1.x + r1.y;
    part[(2 * 8 + ks) * 32 + j] = r2.x + r2.y;
    part[(3 * 8 + ks) * 32 + j] = r3.x + r3.y;
}

// ============================================================================
// Phase 1: input projections (also zeroes the scan barrier counters)
// ============================================================================
__global__ __launch_bounds__(256) void proj_kernel(
    const float* __restrict__ X,
    const float* __restrict__ Wf, const float* __restrict__ bf,
    const float* __restrict__ Wh, const float* __restrict__ bh)
{
    if (blockIdx.x == 0 && blockIdx.y == 0 && blockIdx.z == 0)
        g_cnt[threadIdx.x] = 0u;

    const float* W  = blockIdx.z ? Wh : Wf;
    const float* bv = blockIdx.z ? bh : bf;
    float* out = blockIdx.z ? g_xh : g_xf;

    __shared__ float As[16][132];
    __shared__ float Bs[16][68];

    const int tid = threadIdx.x;
    const int tx = tid & 15;
    const int ty = tid >> 4;
    const long m0 = (long)blockIdx.x * 128;
    const int  n0 = blockIdx.y * 64;

    u64 acc[4][4];
    #pragma unroll
    for (int p = 0; p < 4; p++)
        #pragma unroll
        for (int c = 0; c < 4; c++) acc[p][c] = 0ull;

    for (int k0 = 0; k0 < IDIM; k0 += 16) {
        #pragma unroll
        for (int q0 = 0; q0 < 2; q0++) {
            int q = tid + q0 * 256;
            int row = q >> 2;
            int kc  = (q & 3) * 4;
            float4 v = *(const float4*)&X[(m0 + row) * IDIM + k0 + kc];
            As[kc+0][row] = v.x; As[kc+1][row] = v.y;
            As[kc+2][row] = v.z; As[kc+3][row] = v.w;
        }
        {
            int row = tid >> 2;
            int kc  = (tid & 3) * 4;
            float4 v = *(const float4*)&W[(n0 + row) * IDIM + k0 + kc];
            Bs[kc+0][row] = v.x; Bs[kc+1][row] = v.y;
            Bs[kc+2][row] = v.z; Bs[kc+3][row] = v.w;
        }
        __syncthreads();

        #pragma unroll
        for (int kk = 0; kk < 16; kk++) {
            float4 a0 = *(const float4*)&As[kk][ty * 8];
            float4 a1 = *(const float4*)&As[kk][ty * 8 + 4];
            float4 b4 = *(const float4*)&Bs[kk][tx * 4];
            u64 a2[4] = { pack2(a0.x, a0.y), pack2(a0.z, a0.w),
                          pack2(a1.x, a1.y), pack2(a1.z, a1.w) };
            u64 bb[4] = { pack2(b4.x, b4.x), pack2(b4.y, b4.y),
                          pack2(b4.z, b4.z), pack2(b4.w, b4.w) };
            #pragma unroll
            for (int p = 0; p < 4; p++)
                #pragma unroll
                for (int c = 0; c < 4; c++)
                    acc[p][c] = ffma2(a2[p], bb[c], acc[p][c]);
        }
        __syncthreads();
    }

    float4 bias4 = *(const float4*)&bv[n0 + tx * 4];
    #pragma unroll
    for (int p = 0; p < 4; p++) {
        float2 c0 = unpack2(acc[p][0]);
        float2 c1 = unpack2(acc[p][1]);
        float2 c2 = unpack2(acc[p][2]);
        float2 c3 = unpack2(acc[p][3]);
        long mlo = m0 + ty * 8 + 2 * p;
        float4 lo = make_float4(c0.x + bias4.x, c1.x + bias4.y,
                                c2.x + bias4.z, c3.x + bias4.w);
        float4 hi = make_float4(c0.y + bias4.x, c1.y + bias4.y,
                                c2.y + bias4.z, c3.y + bias4.w);
        *(float4*)&out[mlo * HDIM + n0 + tx * 4]       = lo;
        *(float4*)&out[(mlo + 1) * HDIM + n0 + tx * 4] = hi;
    }
}

// ============================================================================
// Phase 2 (primary): cluster-16 scan, DSMEM push exchange, dual 4-row chains,
// register-resident weights.
// ============================================================================
__global__ __launch_bounds__(256, 1) void scan_cluster(
    const float* __restrict__ h0,
    const float* __restrict__ Whf,
    const float* __restrict__ Whh,
    float* __restrict__ out)
{
    __shared__ float h_s[8 * 512];
    __shared__ float g_s[8 * 512];
    __shared__ float part0[4 * 8 * 32];
    __shared__ float part1[4 * 8 * 32];
    __shared__ __align__(8) u64 mbar[4];   // g0, g1, h0, h1

    const int tid = threadIdx.x;
    const int grp = blockIdx.x >> 4;
    const int j0  = (blockIdx.x & 15) * COLS_PER_BLK;
    const int b0  = grp * B_PER_GROUP;

    const int j  = tid & 31;
    const int ks = tid >> 5;
    const int kb = ks * 64;
    const int chn = tid >> 7;
    const int fb  = (tid >> 5) & 3;
    const int fj  = tid & 31;
    const int frow = chn * 4 + fb;

    // weights: register-resident, pre-packed
    u64 wf2[32], wh2[32];
    #pragma unroll
    for (int i = 0; i < 16; i++) {
        float4 v = *(const float4*)&Whf[(j0 + j) * HDIM + kb + 4 * i];
        wf2[2*i] = pack2(v.x, v.y); wf2[2*i+1] = pack2(v.z, v.w);
    }
    #pragma unroll
    for (int i = 0; i < 16; i++) {
        float4 v = *(const float4*)&Whh[(j0 + j) * HDIM + kb + 4 * i];
        wh2[2*i] = pack2(v.x, v.y); wh2[2*i+1] = pack2(v.z, v.w);
    }

    {
        const float4* src = (const float4*)&h0[b0 * HDIM];
        float4* dst = (float4*)h_s;
        for (int i = tid; i < 1024; i += 256) dst[i] = src[i];
    }
    if (tid == 0) {
        #pragma unroll
        for (int i = 0; i < 4; i++) mbar_init(smem_u32(&mbar[i]), 16);
    }
    __syncthreads();
    CLUSTER_SYNC();

    const uint32_t bar_g0 = smem_u32(&mbar[0]);
    const uint32_t bar_g1 = smem_u32(&mbar[1]);
    const uint32_t bar_h0 = smem_u32(&mbar[2]);
    const uint32_t bar_h1 = smem_u32(&mbar[3]);
    const uint32_t g_addr = smem_u32(&g_s[frow * 512 + j0 + fj]);
    const uint32_t h_addr = smem_u32(&h_s[frow * 512 + j0 + fj]);

    float hp = h_s[frow * 512 + j0 + fj];
    float f_reg = 0.0f;
    float* partF = chn ? part1 : part0;

    for (int t = 0; t < T_STEPS; t++) {
        const long xoff = (long)t * (BATCH * HDIM) + (long)(b0 + frow) * HDIM + j0 + fj;
        const float xf_v = __ldcs(&g_xf[xoff]);
        const float xh_v = __ldcs(&g_xh[xoff]);
        const uint32_t par = t & 1;

        // A0: f-gate, rows 0-3
        gemm4(wf2, h_s, kb, part0, ks, j);
        __syncthreads();
        if (chn == 0) {
            float s = xf_v;
            #pragma unroll
            for (int q = 0; q < 8; q++) s += part0[(fb * 8 + q) * 32 + fj];
            f_reg = sigmoid_f(s);
            push16(g_addr, f_reg * hp);
        }
        __syncthreads();
        if (tid == 0) arrive_all16(bar_g0);
        if (t > 0) mbar_wait(bar_h1, (t - 1) & 1);

        // A1: f-gate, rows 4-7
        gemm4(wf2, h_s + 4 * 512, kb, part1, ks, j);
        __syncthreads();
        if (chn == 1) {
            float s = xf_v;
            #pragma unroll
            for (int q = 0; q < 8; q++) s += part1[(fb * 8 + q) * 32 + fj];
            f_reg = sigmoid_f(s);
            push16(g_addr, f_reg * hp);
        }
        __syncthreads();
        if (tid == 0) arrive_all16(bar_g1);
        mbar_wait(bar_g0, par);

        // B0: candidate, rows 0-3
        gemm4(wh2, g_s, kb, part0, ks, j);
        __syncthreads();
        if (chn == 0) {
            float s = xh_v;
            #pragma unroll
            for (int q = 0; q < 8; q++) s += part0[(fb * 8 + q) * 32 + fj];
            float ht = tanh_f(s);
            float hn = fmaf(f_reg, ht - hp, hp);
            __stcs(&out[((long)t * BATCH + (b0 + frow)) * HDIM + j0 + fj], hn);
            if (t == T_STEPS - 1)
                out[(long)T_STEPS * BATCH * HDIM + (b0 + frow) * HDIM + j0 + fj] = hn;
            hp = hn;
            push16(h_addr, hn);
        }
        __syncthreads();
        if (tid == 0) arrive_all16(bar_h0);
        mbar_wait(bar_g1, par);

        // B1: candidate, rows 4-7
        gemm4(wh2, g_s + 4 * 512, kb, part1, ks, j);
        __syncthreads();
        if (chn == 1) {
            float s = xh_v;
            #pragma unroll
            for (int q = 0; q < 8; q++) s += part1[(fb * 8 + q) * 32 + fj];
            float ht = tanh_f(s);
            float hn = fmaf(f_reg, ht - hp, hp);
            __stcs(&out[((long)t * BATCH + (b0 + frow)) * HDIM + j0 + fj], hn);
            if (t == T_STEPS - 1)
                out[(long)T_STEPS * BATCH * HDIM + (b0 + frow) * HDIM + j0 + fj] = hn;
            hp = hn;
            push16(h_addr, hn);
        }
        __syncthreads();
        if (tid == 0) arrive_all16(bar_h1);
        mbar_wait(bar_h0, par);
    }
    CLUSTER_SYNC();
    (void)partF;
}

// ============================================================================
// Phase 2 (fallback): same dual-chain structure, exchange via L2 + 4
// release/acquire counters per group, register-resident weights.
// ============================================================================
__global__ __launch_bounds__(256, 1) void scan_global(
    const float* __restrict__ h0,
    const float* __restrict__ Whf,
    const float* __restrict__ Whh,
    float* __restrict__ out)
{
    __shared__ float h_s[8 * 512];
    __shared__ float g_s[8 * 512];
    __shared__ float part0[4 * 8 * 32];
    __shared__ float part1[4 * 8 * 32];

    const int tid = threadIdx.x;
    const int grp = blockIdx.x >> 4;
    const int j0  = (blockIdx.x & 15) * COLS_PER_BLK;
    const int b0  = grp * B_PER_GROUP;

    const int j  = tid & 31;
    const int ks = tid >> 5;
    const int kb = ks * 64;
    const int chn = tid >> 7;
    const int fb  = (tid >> 5) & 3;
    const int fj  = tid & 31;
    const int frow = chn * 4 + fb;

    u64 wf2[32], wh2[32];
    #pragma unroll
    for (int i = 0; i < 16; i++) {
        float4 v = *(const float4*)&Whf[(j0 + j) * HDIM + kb + 4 * i];
        wf2[2*i] = pack2(v.x, v.y); wf2[2*i+1] = pack2(v.z, v.w);
    }
    #pragma unroll
    for (int i = 0; i < 16; i++) {
        float4 v = *(const float4*)&Whh[(j0 + j) * HDIM + kb + 4 * i];
        wh2[2*i] = pack2(v.x, v.y); wh2[2*i+1] = pack2(v.z, v.w);
    }

    {
        const float4* src = (const float4*)&h0[b0 * HDIM];
        float4* dst = (float4*)h_s;
        for (int i = tid; i < 1024; i += 256) dst[i] = src[i];
    }
    __syncthreads();

    unsigned int* cg0 = &g_cnt[grp * 32 + 0];
    unsigned int* cg1 = &g_cnt[grp * 32 + 8];
    unsigned int* ch0 = &g_cnt[grp * 32 + 16];
    unsigned int* ch1 = &g_cnt[grp * 32 + 24];

    float hp = h_s[frow * 512 + j0 + fj];
    float f_reg = 0.0f;

    // gather helpers: 4 rows (rb..rb+3) x 512 cols = 512 float4, 2 per thread
    #define GATHER4(dstbuf, srcbuf, rb)  do {                                  \
        const float4* _s = (const float4*)&srcbuf[(b0 + (rb)) * HDIM];         \
        float4* _d = (float4*)&dstbuf[(rb) * 512];                             \
        _d[tid]       = ldcg4(&_s[tid]);                                       \
        _d[tid + 256] = ldcg4(&_s[tid + 256]);                                 \
    } while (0)

    for (int t = 0; t < T_STEPS; t++) {
        const unsigned int tgt = (unsigned int)(t + 1) * BLKS_PER_GROUP;
        const long xoff = (long)t * (BATCH * HDIM) + (long)(b0 + frow) * HDIM + j0 + fj;
        const float xf_v = __ldcs(&g_xf[xoff]);
        const float xh_v = __ldcs(&g_xh[xoff]);

        // A0
        gemm4(wf2, h_s, kb, part0, ks, j);
        __syncthreads();
        if (chn == 0) {
            float s = xf_v;
            #pragma unroll
            for (int q = 0; q < 8; q++) s += part0[(fb * 8 + q) * 32 + fj];
            f_reg = sigmoid_f(s);
            g_gbuf[(b0 + frow) * HDIM + j0 + fj] = f_reg * hp;
        }
        __syncthreads();
        if (tid == 0) {
            red_release(cg0);
            if (t > 0) while (ld_acq(ch1) < tgt - BLKS_PER_GROUP) { }
        }
        __syncthreads();
        if (t > 0) { GATHER4(h_s, g_hbuf, 4); __syncthreads(); }

        // A1
        gemm4(wf2, h_s + 4 * 512, kb, part1, ks, j);
        __syncthreads();
        if (chn == 1) {
            float s = xf_v;
            #pragma unroll
            for (int q = 0; q < 8; q++) s += part1[(fb * 8 + q) * 32 + fj];
            f_reg = sigmoid_f(s);
            g_gbuf[(b0 + frow) * HDIM + j0 + fj] = f_reg * hp;
        }
        __syncthreads();
        if (tid == 0) {
            red_release(cg1);
            while (ld_acq(cg0) < tgt) { }
        }
        __syncthreads();
        GATHER4(g_s, g_gbuf, 0);
        __syncthreads();

        // B0
        gemm4(wh2, g_s, kb, part0, ks, j);
        __syncthreads();
        if (chn == 0) {
            float s = xh_v;
            #pragma unroll
            for (int q = 0; q < 8; q++) s += part0[(fb * 8 + q) * 32 + fj];
            float ht = tanh_f(s);
            float hn = fmaf(f_reg, ht - hp, hp);
            __stcs(&out[((long)t * BATCH + (b0 + frow)) * HDIM + j0 + fj], hn);
            if (t == T_STEPS - 1)
                out[(long)T_STEPS * BATCH * HDIM + (b0 + frow) * HDIM + j0 + fj] = hn;
            hp = hn;
            g_hbuf[(b0 + frow) * HDIM + j0 + fj] = hn;
        }
        __syncthreads();
        if (tid == 0) {
            red_release(ch0);
            while (ld_acq(cg1) < tgt) { }
        }
        __syncthreads();
        GATHER4(g_s, g_gbuf, 4);
        __syncthreads();

        // B1
        gemm4(wh2, g_s + 4 * 512, kb, part1, ks, j);
        __syncthreads();
        if (chn == 1) {
            float s = xh_v;
            #pragma unroll
            for (int q = 0; q < 8; q++) s += part1[(fb * 8 + q) * 32 + fj];
            float ht = tanh_f(s);
            float hn = fmaf(f_reg, ht - hp, hp);
            __stcs(&out[((long)t * BATCH + (b0 + frow)) * HDIM + j0 + fj], hn);
            if (t == T_STEPS - 1)
                out[(long)T_STEPS * BATCH * HDIM + (b0 + frow) * HDIM + j0 + fj] = hn;
            hp = hn;
            g_hbuf[(b0 + frow) * HDIM + j0 + fj] = hn;
        }
        __syncthreads();
        if (tid == 0) {
            red_release(ch1);
            while (ld_acq(ch0) < tgt) { }
        }
        __syncthreads();
        GATHER4(h_s, g_hbuf, 0);
        __syncthreads();
    }
    #undef GATHER4
}

// ============================================================================
extern "C" void kernel_launch(void* const* d_in, const int* in_sizes, int n_in,
                              void* d_out, int out_size)
{
    const float* x   = (const float*)d_in[0];
    const float* h0  = (const float*)d_in[1];
    const float* Wxf = (const float*)d_in[2];
    const float* Whf = (const float*)d_in[3];
    const float* bf  = (const float*)d_in[4];
    const float* Wxh = (const float*)d_in[5];
    const float* Whh = (const float*)d_in[6];
    const float* bh  = (const float*)d_in[7];
    float* out = (float*)d_out;

    cudaFuncSetAttribute(scan_cluster,
                         cudaFuncAttributeNonPortableClusterSizeAllowed, 1);

    dim3 pgrid((T_STEPS * BATCH) / 128, HDIM / 64, 2);
    proj_kernel<<<pgrid, 256>>>(x, Wxf, bf, Wxh, bh);

    // Gate: MaxPotentialClusterSize is valid for non-portable sizes
    // (MaxActiveClusters is NOT — it fails for size > 8, the R3 bug).
    int maxc = 0;
    {
        cudaLaunchConfig_t qcfg = {};
        qcfg.gridDim = dim3(N_GROUPS * BLKS_PER_GROUP, 1, 1);
        qcfg.blockDim = dim3(256, 1, 1);
        qcfg.dynamicSmemBytes = 0;
        cudaError_t qe = cudaOccupancyMaxPotentialClusterSize(&maxc, scan_cluster, &qcfg);
        if (qe != cudaSuccess) { cudaGetLastError(); maxc = 0; }
    }

    if (maxc >= 16) {
        cudaLaunchConfig_t cfg = {};
        cfg.gridDim = dim3(N_GROUPS * BLKS_PER_GROUP, 1, 1);
        cfg.blockDim = dim3(256, 1, 1);
        cfg.dynamicSmemBytes = 0;
        cfg.stream = 0;
        cudaLaunchAttribute attrs[1];
        attrs[0].id = cudaLaunchAttributeClusterDimension;
        attrs[0].val.clusterDim.x = 16;
        attrs[0].val.clusterDim.y = 1;
        attrs[0].val.clusterDim.z = 1;
        cfg.attrs = attrs;
        cfg.numAttrs = 1;
        cudaLaunchKernelEx(&cfg, scan_cluster, h0, Whf, Whh, out);
    } else {
        scan_global<<<N_GROUPS * BLKS_PER_GROUP, 256>>>(h0, Whf, Whh, out);
    }
}

// round 5
// speedup vs baseline: 3.4824x; 3.4824x over previous
#include <cuda_runtime.h>
#include <cstdint>

#define T_STEPS 2048
#define BATCH   64
#define IDIM    512
#define HDIM    512

#define N_GROUPS 8
#define BLKS_PER_GROUP 16
#define B_PER_GROUP 8
#define COLS_PER_BLK 32

typedef unsigned long long u64;

// ---------------- scratch (static device allocations) ----------------------
__device__ float g_xf[(long)T_STEPS * BATCH * HDIM];
__device__ float g_xh[(long)T_STEPS * BATCH * HDIM];
__device__ float g_hbuf[BATCH * HDIM];
__device__ float g_gbuf[BATCH * HDIM];
__device__ unsigned int g_cnt[N_GROUPS * 32];   // 4 counters/group, 32B apart

// ---------------- packed f32x2 helpers --------------------------------------
__device__ __forceinline__ u64 pack2(float x, float y) {
    u64 r; asm("mov.b64 %0, {%1, %2};" : "=l"(r) : "f"(x), "f"(y)); return r;
}
__device__ __forceinline__ u64 ffma2(u64 a, u64 b, u64 c) {
    u64 d; asm("fma.rn.f32x2 %0, %1, %2, %3;" : "=l"(d) : "l"(a), "l"(b), "l"(c));
    return d;
}
__device__ __forceinline__ float2 unpack2(u64 a) {
    float2 r; asm("mov.b64 {%0, %1}, %2;" : "=f"(r.x), "=f"(r.y) : "l"(a)); return r;
}
__device__ __forceinline__ float4 ldcg4(const float4* p) {
    float4 v;
    asm volatile("ld.global.cg.v4.f32 {%0,%1,%2,%3}, [%4];"
                 : "=f"(v.x), "=f"(v.y), "=f"(v.z), "=f"(v.w) : "l"(p));
    return v;
}
__device__ __forceinline__ void red_release(unsigned int* p) {
    asm volatile("red.release.gpu.global.add.u32 [%0], 1;" :: "l"(p) : "memory");
}
__device__ __forceinline__ unsigned int ld_acq(const unsigned int* p) {
    unsigned int v;
    asm volatile("ld.acquire.gpu.global.u32 %0, [%1];" : "=r"(v) : "l"(p) : "memory");
    return v;
}

__device__ __forceinline__ float sigmoid_f(float x) {
    return 1.0f / (1.0f + __expf(-x));
}
__device__ __forceinline__ float tanh_f(float x) {
    return 1.0f - 2.0f / (__expf(2.0f * x) + 1.0f);
}

// 4-row GEMM half-phase: weights register-resident (pre-packed u64),
// h/g rows read as uniform-address broadcast LDS.128.
__device__ __forceinline__ void gemm4(const u64* __restrict__ w2,
                                      const float* __restrict__ src,
                                      int kb, float* __restrict__ part,
                                      int ks, int j)
{
    u64 a0 = 0ull, a1 = 0ull, a2 = 0ull, a3 = 0ull;
    #pragma unroll
    for (int i = 0; i < 16; i++) {
        u64 wlo = w2[2 * i], whi = w2[2 * i + 1];
        float4 x0 = *(const float4*)&src[0 * 512 + kb + 4 * i];
        float4 x1 = *(const float4*)&src[1 * 512 + kb + 4 * i];
        float4 x2 = *(const float4*)&src[2 * 512 + kb + 4 * i];
        float4 x3 = *(const float4*)&src[3 * 512 + kb + 4 * i];
        a0 = ffma2(wlo, pack2(x0.x, x0.y), a0);
        a0 = ffma2(whi, pack2(x0.z, x0.w), a0);
        a1 = ffma2(wlo, pack2(x1.x, x1.y), a1);
        a1 = ffma2(whi, pack2(x1.z, x1.w), a1);
        a2 = ffma2(wlo, pack2(x2.x, x2.y), a2);
        a2 = ffma2(whi, pack2(x2.z, x2.w), a2);
        a3 = ffma2(wlo, pack2(x3.x, x3.y), a3);
        a3 = ffma2(whi, pack2(x3.z, x3.w), a3);
    }
    float2 r0 = unpack2(a0), r1 = unpack2(a1), r2 = unpack2(a2), r3 = unpack2(a3);
    part[(0 * 8 + ks) * 32 + j] = r0.x + r0.y;
    part[(1 * 8 + ks) * 32 + j] = r1.x + r1.y;
    part[(2 * 8 + ks) * 32 + j] = r2.x + r2.y;
    part[(3 * 8 + ks) * 32 + j] = r3.x + r3.y;
}

// ============================================================================
// Phase 1: input projections (also zeroes the scan barrier counters)
// ============================================================================
__global__ __launch_bounds__(256) void proj_kernel(
    const float* __restrict__ X,
    const float* __restrict__ Wf, const float* __restrict__ bf,
    const float* __restrict__ Wh, const float* __restrict__ bh)
{
    if (blockIdx.x == 0 && blockIdx.y == 0 && blockIdx.z == 0)
        g_cnt[threadIdx.x] = 0u;

    const float* W  = blockIdx.z ? Wh : Wf;
    const float* bv = blockIdx.z ? bh : bf;
    float* out = blockIdx.z ? g_xh : g_xf;

    __shared__ float As[16][132];
    __shared__ float Bs[16][68];

    const int tid = threadIdx.x;
    const int tx = tid & 15;
    const int ty = tid >> 4;
    const long m0 = (long)blockIdx.x * 128;
    const int  n0 = blockIdx.y * 64;

    u64 acc[4][4];
    #pragma unroll
    for (int p = 0; p < 4; p++)
        #pragma unroll
        for (int c = 0; c < 4; c++) acc[p][c] = 0ull;

    for (int k0 = 0; k0 < IDIM; k0 += 16) {
        #pragma unroll
        for (int q0 = 0; q0 < 2; q0++) {
            int q = tid + q0 * 256;
            int row = q >> 2;
            int kc  = (q & 3) * 4;
            float4 v = *(const float4*)&X[(m0 + row) * IDIM + k0 + kc];
            As[kc+0][row] = v.x; As[kc+1][row] = v.y;
            As[kc+2][row] = v.z; As[kc+3][row] = v.w;
        }
        {
            int row = tid >> 2;
            int kc  = (tid & 3) * 4;
            float4 v = *(const float4*)&W[(n0 + row) * IDIM + k0 + kc];
            Bs[kc+0][row] = v.x; Bs[kc+1][row] = v.y;
            Bs[kc+2][row] = v.z; Bs[kc+3][row] = v.w;
        }
        __syncthreads();

        #pragma unroll
        for (int kk = 0; kk < 16; kk++) {
            float4 a0 = *(const float4*)&As[kk][ty * 8];
            float4 a1 = *(const float4*)&As[kk][ty * 8 + 4];
            float4 b4 = *(const float4*)&Bs[kk][tx * 4];
            u64 a2[4] = { pack2(a0.x, a0.y), pack2(a0.z, a0.w),
                          pack2(a1.x, a1.y), pack2(a1.z, a1.w) };
            u64 bb[4] = { pack2(b4.x, b4.x), pack2(b4.y, b4.y),
                          pack2(b4.z, b4.z), pack2(b4.w, b4.w) };
            #pragma unroll
            for (int p = 0; p < 4; p++)
                #pragma unroll
                for (int c = 0; c < 4; c++)
                    acc[p][c] = ffma2(a2[p], bb[c], acc[p][c]);
        }
        __syncthreads();
    }

    float4 bias4 = *(const float4*)&bv[n0 + tx * 4];
    #pragma unroll
    for (int p = 0; p < 4; p++) {
        float2 c0 = unpack2(acc[p][0]);
        float2 c1 = unpack2(acc[p][1]);
        float2 c2 = unpack2(acc[p][2]);
        float2 c3 = unpack2(acc[p][3]);
        long mlo = m0 + ty * 8 + 2 * p;
        float4 lo = make_float4(c0.x + bias4.x, c1.x + bias4.y,
                                c2.x + bias4.z, c3.x + bias4.w);
        float4 hi = make_float4(c0.y + bias4.x, c1.y + bias4.y,
                                c2.y + bias4.z, c3.y + bias4.w);
        *(float4*)&out[mlo * HDIM + n0 + tx * 4]       = lo;
        *(float4*)&out[(mlo + 1) * HDIM + n0 + tx * 4] = hi;
    }
}

// ============================================================================
// Phase 2: persistent scan. Dual 4-row chains, register-resident weights,
// L2 exchange with 4 staggered release/acquire counters per group.
// Each wait targets a counter released one full GEMM phase earlier, so the
// L2 RTT is hidden behind compute.
// ============================================================================
__global__ __launch_bounds__(256, 1) void scan_global(
    const float* __restrict__ h0,
    const float* __restrict__ Whf,
    const float* __restrict__ Whh,
    float* __restrict__ out)
{
    __shared__ float h_s[8 * 512];
    __shared__ float g_s[8 * 512];
    __shared__ float part0[4 * 8 * 32];
    __shared__ float part1[4 * 8 * 32];

    const int tid = threadIdx.x;
    const int grp = blockIdx.x >> 4;
    const int j0  = (blockIdx.x & 15) * COLS_PER_BLK;
    const int b0  = grp * B_PER_GROUP;

    const int j  = tid & 31;
    const int ks = tid >> 5;
    const int kb = ks * 64;
    const int chn = tid >> 7;
    const int fb  = (tid >> 5) & 3;
    const int fj  = tid & 31;
    const int frow = chn * 4 + fb;

    u64 wf2[32], wh2[32];
    #pragma unroll
    for (int i = 0; i < 16; i++) {
        float4 v = *(const float4*)&Whf[(j0 + j) * HDIM + kb + 4 * i];
        wf2[2*i] = pack2(v.x, v.y); wf2[2*i+1] = pack2(v.z, v.w);
    }
    #pragma unroll
    for (int i = 0; i < 16; i++) {
        float4 v = *(const float4*)&Whh[(j0 + j) * HDIM + kb + 4 * i];
        wh2[2*i] = pack2(v.x, v.y); wh2[2*i+1] = pack2(v.z, v.w);
    }

    {
        const float4* src = (const float4*)&h0[b0 * HDIM];
        float4* dst = (float4*)h_s;
        for (int i = tid; i < 1024; i += 256) dst[i] = src[i];
    }
    __syncthreads();

    unsigned int* cg0 = &g_cnt[grp * 32 + 0];
    unsigned int* cg1 = &g_cnt[grp * 32 + 8];
    unsigned int* ch0 = &g_cnt[grp * 32 + 16];
    unsigned int* ch1 = &g_cnt[grp * 32 + 24];

    float hp = h_s[frow * 512 + j0 + fj];
    float f_reg = 0.0f;

    // gather: 4 rows (rb..rb+3) x 512 cols = 512 float4, 2 per thread
    #define GATHER4(dstbuf, srcbuf, rb)  do {                                  \
        const float4* _s = (const float4*)&srcbuf[(b0 + (rb)) * HDIM];         \
        float4* _d = (float4*)&dstbuf[(rb) * 512];                             \
        _d[tid]       = ldcg4(&_s[tid]);                                       \
        _d[tid + 256] = ldcg4(&_s[tid + 256]);                                 \
    } while (0)

    for (int t = 0; t < T_STEPS; t++) {
        const unsigned int tgt = (unsigned int)(t + 1) * BLKS_PER_GROUP;
        const long xoff = (long)t * (BATCH * HDIM) + (long)(b0 + frow) * HDIM + j0 + fj;
        const float xf_v = __ldcs(&g_xf[xoff]);
        const float xh_v = __ldcs(&g_xh[xoff]);

        // A0: f gate, rows 0-3 (h rows 0-3 gathered at end of prev step)
        gemm4(wf2, h_s, kb, part0, ks, j);
        __syncthreads();
        if (chn == 0) {
            float s = xf_v;
            #pragma unroll
            for (int q = 0; q < 8; q++) s += part0[(fb * 8 + q) * 32 + fj];
            f_reg = sigmoid_f(s);
            g_gbuf[(b0 + frow) * HDIM + j0 + fj] = f_reg * hp;
        }
        __syncthreads();
        if (tid == 0) {
            red_release(cg0);
            if (t > 0) while (ld_acq(ch1) < tgt - BLKS_PER_GROUP) { }
        }
        __syncthreads();
        if (t > 0) { GATHER4(h_s, g_hbuf, 4); __syncthreads(); }

        // A1: f gate, rows 4-7
        gemm4(wf2, h_s + 4 * 512, kb, part1, ks, j);
        __syncthreads();
        if (chn == 1) {
            float s = xf_v;
            #pragma unroll
            for (int q = 0; q < 8; q++) s += part1[(fb * 8 + q) * 32 + fj];
            f_reg = sigmoid_f(s);
            g_gbuf[(b0 + frow) * HDIM + j0 + fj] = f_reg * hp;
        }
        __syncthreads();
        if (tid == 0) {
            red_release(cg1);
            while (ld_acq(cg0) < tgt) { }
        }
        __syncthreads();
        GATHER4(g_s, g_gbuf, 0);
        __syncthreads();

        // B0: candidate, rows 0-3
        gemm4(wh2, g_s, kb, part0, ks, j);
        __syncthreads();
        if (chn == 0) {
            float s = xh_v;
            #pragma unroll
            for (int q = 0; q < 8; q++) s += part0[(fb * 8 + q) * 32 + fj];
            float ht = tanh_f(s);
            float hn = fmaf(f_reg, ht - hp, hp);
            __stcs(&out[((long)t * BATCH + (b0 + frow)) * HDIM + j0 + fj], hn);
            if (t == T_STEPS - 1)
                out[(long)T_STEPS * BATCH * HDIM + (b0 + frow) * HDIM + j0 + fj] = hn;
            hp = hn;
            g_hbuf[(b0 + frow) * HDIM + j0 + fj] = hn;
        }
        __syncthreads();
        if (tid == 0) {
            red_release(ch0);
            while (ld_acq(cg1) < tgt) { }
        }
        __syncthreads();
        GATHER4(g_s, g_gbuf, 4);
        __syncthreads();

        // B1: candidate, rows 4-7
        gemm4(wh2, g_s + 4 * 512, kb, part1, ks, j);
        __syncthreads();
        if (chn == 1) {
            float s = xh_v;
            #pragma unroll
            for (int q = 0; q < 8; q++) s += part1[(fb * 8 + q) * 32 + fj];
            float ht = tanh_f(s);
            float hn = fmaf(f_reg, ht - hp, hp);
            __stcs(&out[((long)t * BATCH + (b0 + frow)) * HDIM + j0 + fj], hn);
            if (t == T_STEPS - 1)
                out[(long)T_STEPS * BATCH * HDIM + (b0 + frow) * HDIM + j0 + fj] = hn;
            hp = hn;
            g_hbuf[(b0 + frow) * HDIM + j0 + fj] = hn;
        }
        __syncthreads();
        if (tid == 0) {
            red_release(ch1);
            while (ld_acq(ch0) < tgt) { }
        }
        __syncthreads();
        GATHER4(h_s, g_hbuf, 0);
        __syncthreads();
    }
    #undef GATHER4
}

// ============================================================================
extern "C" void kernel_launch(void* const* d_in, const int* in_sizes, int n_in,
                              void* d_out, int out_size)
{
    const float* x   = (const float*)d_in[0];
    const float* h0  = (const float*)d_in[1];
    const float* Wxf = (const float*)d_in[2];
    const float* Whf = (const float*)d_in[3];
    const float* bf  = (const float*)d_in[4];
    const float* Wxh = (const float*)d_in[5];
    const float* Whh = (const float*)d_in[6];
    const float* bh  = (const float*)d_in[7];
    float* out = (float*)d_out;

    dim3 pgrid((T_STEPS * BATCH) / 128, HDIM / 64, 2);
    proj_kernel<<<pgrid, 256>>>(x, Wxf, bf, Wxh, bh);

    scan_global<<<N_GROUPS * BLKS_PER_GROUP, 256>>>(h0, Whf, Whh, out);
}

// round 7
// speedup vs baseline: 3.9923x; 1.1464x over previous
#include <cuda_runtime.h>
#include <cstdint>

#define T_STEPS 2048
#define BATCH   64
#define IDIM    512
#define HDIM    512

#define N_GROUPS 16           // groups of 4 batch rows
#define BLKS_PER_GROUP 16     // blocks per group (32 H-cols each)
#define B_PER_GROUP 4
#define COLS_PER_BLK 32

typedef unsigned long long u64;

// ---------------- scratch -----------------------------------------------
__device__ float g_xf[(long)T_STEPS * BATCH * HDIM];
__device__ float g_xh[(long)T_STEPS * BATCH * HDIM];
__device__ float g_hbuf[BATCH * HDIM];
__device__ float g_gbuf[BATCH * HDIM];
__device__ unsigned int g_cnt[N_GROUPS * 16];   // 2 counters/group (offs 0, 8)

// ---------------- packed f32x2 helpers -----------------------------------
__device__ __forceinline__ u64 pack2(float x, float y) {
    u64 r; asm("mov.b64 %0, {%1, %2};" : "=l"(r) : "f"(x), "f"(y)); return r;
}
__device__ __forceinline__ u64 ffma2(u64 a, u64 b, u64 c) {
    u64 d; asm("fma.rn.f32x2 %0, %1, %2, %3;" : "=l"(d) : "l"(a), "l"(b), "l"(c));
    return d;
}
__device__ __forceinline__ float2 unpack2(u64 a) {
    float2 r; asm("mov.b64 {%0, %1}, %2;" : "=f"(r.x), "=f"(r.y) : "l"(a)); return r;
}
__device__ __forceinline__ float4 ldcg4(const float4* p) {
    float4 v;
    asm volatile("ld.global.cg.v4.f32 {%0,%1,%2,%3}, [%4];"
                 : "=f"(v.x), "=f"(v.y), "=f"(v.z), "=f"(v.w) : "l"(p));
    return v;
}
__device__ __forceinline__ void red_release(unsigned int* p) {
    asm volatile("red.release.gpu.global.add.u32 [%0], 1;" :: "l"(p) : "memory");
}
__device__ __forceinline__ unsigned int ld_acq(const unsigned int* p) {
    unsigned int v;
    asm volatile("ld.acquire.gpu.global.u32 %0, [%1];" : "=r"(v) : "l"(p) : "memory");
    return v;
}
__device__ __forceinline__ float sigmoid_f(float x) {
    return __fdividef(1.0f, 1.0f + __expf(-x));
}
__device__ __forceinline__ float tanh_ap(float x) {
    float y; asm("tanh.approx.f32 %0, %1;" : "=f"(y) : "f"(x)); return y;
}

// ============================================================================
// Phase 1: input projections. Block (0,0,0) zeroes counters; blocks
// (x<16,0,0) seed g_hbuf from h0.
// ============================================================================
__global__ __launch_bounds__(256) void proj_kernel(
    const float* __restrict__ X,  const float* __restrict__ h0,
    const float* __restrict__ Wf, const float* __restrict__ bf,
    const float* __restrict__ Wh, const float* __restrict__ bh)
{
    if (blockIdx.y == 0 && blockIdx.z == 0) {
        if (blockIdx.x == 0) g_cnt[threadIdx.x] = 0u;
        if (blockIdx.x < 16) {
            const float4* s = (const float4*)&h0[blockIdx.x * 4 * HDIM];
            float4* d = (float4*)&g_hbuf[blockIdx.x * 4 * HDIM];
            d[threadIdx.x]       = s[threadIdx.x];
            d[threadIdx.x + 256] = s[threadIdx.x + 256];
        }
    }

    const float* W  = blockIdx.z ? Wh : Wf;
    const float* bv = blockIdx.z ? bh : bf;
    float* out = blockIdx.z ? g_xh : g_xf;

    __shared__ float As[16][132];
    __shared__ float Bs[16][68];

    const int tid = threadIdx.x;
    const int tx = tid & 15;
    const int ty = tid >> 4;
    const long m0 = (long)blockIdx.x * 128;
    const int  n0 = blockIdx.y * 64;

    u64 acc[4][4];
    #pragma unroll
    for (int p = 0; p < 4; p++)
        #pragma unroll
        for (int c = 0; c < 4; c++) acc[p][c] = 0ull;

    for (int k0 = 0; k0 < IDIM; k0 += 16) {
        #pragma unroll
        for (int q0 = 0; q0 < 2; q0++) {
            int q = tid + q0 * 256;
            int row = q >> 2;
            int kc  = (q & 3) * 4;
            float4 v = *(const float4*)&X[(m0 + row) * IDIM + k0 + kc];
            As[kc+0][row] = v.x; As[kc+1][row] = v.y;
            As[kc+2][row] = v.z; As[kc+3][row] = v.w;
        }
        {
            int row = tid >> 2;
            int kc  = (tid & 3) * 4;
            float4 v = *(const float4*)&W[(n0 + row) * IDIM + k0 + kc];
            Bs[kc+0][row] = v.x; Bs[kc+1][row] = v.y;
            Bs[kc+2][row] = v.z; Bs[kc+3][row] = v.w;
        }
        __syncthreads();

        #pragma unroll
        for (int kk = 0; kk < 16; kk++) {
            float4 a0 = *(const float4*)&As[kk][ty * 8];
            float4 a1 = *(const float4*)&As[kk][ty * 8 + 4];
            float4 b4 = *(const float4*)&Bs[kk][tx * 4];
            u64 a2[4] = { pack2(a0.x, a0.y), pack2(a0.z, a0.w),
                          pack2(a1.x, a1.y), pack2(a1.z, a1.w) };
            u64 bb[4] = { pack2(b4.x, b4.x), pack2(b4.y, b4.y),
                          pack2(b4.z, b4.z), pack2(b4.w, b4.w) };
            #pragma unroll
            for (int p = 0; p < 4; p++)
                #pragma unroll
                for (int c = 0; c < 4; c++)
                    acc[p][c] = ffma2(a2[p], bb[c], acc[p][c]);
        }
        __syncthreads();
    }

    float4 bias4 = *(const float4*)&bv[n0 + tx * 4];
    #pragma unroll
    for (int p = 0; p < 4; p++) {
        float2 c0 = unpack2(acc[p][0]);
        float2 c1 = unpack2(acc[p][1]);
        float2 c2 = unpack2(acc[p][2]);
        float2 c3 = unpack2(acc[p][3]);
        long mlo = m0 + ty * 8 + 2 * p;
        float4 lo = make_float4(c0.x + bias4.x, c1.x + bias4.y,
                                c2.x + bias4.z, c3.x + bias4.w);
        float4 hi = make_float4(c0.y + bias4.x, c1.y + bias4.y,
                                c2.y + bias4.z, c3.y + bias4.w);
        *(float4*)&out[mlo * HDIM + n0 + tx * 4]       = lo;
        *(float4*)&out[(mlo + 1) * HDIM + n0 + tx * 4] = hi;
    }
}

// ============================================================================
// Phase 2: persistent scan. 256 blocks of 128 threads, 2 resident per SM
// (mutual latency hiding). Group = 4 batch rows x 16 blocks. Warp w owns
// k-slice [w*128, w*128+128) for the GEMMs and batch row w for finalize.
// Wf register-resident; Wh in SMEM (conflict-free slices). Lane-0 polls +
// __syncwarp broadcast; per-warp releases; only 2 block-wide bars per step.
// ============================================================================
#define WH_STRIDE 132
#define SCAN_SMEM ((128 * WH_STRIDE + 4 * 512 + 512 + 512) * 4)

__global__ void __launch_bounds__(128, 2) scan_kernel(
    const float* __restrict__ h0,
    const float* __restrict__ Whf,
    const float* __restrict__ Whh,
    float* __restrict__ out)
{
    extern __shared__ float smem[];
    float* whs   = smem;                     // 128 slices x 132
    float* srcs  = whs + 128 * WH_STRIDE;    // 4 warps x (4 rows x 128)
    float* partA = srcs + 4 * 512;           // [row][ks][j] 4*4*32
    float* partB = partA + 512;

    const int tid = threadIdx.x;
    const int j   = tid & 31;      // lane = column within block
    const int w   = tid >> 5;      // warp = k-slice index AND finalize row
    const int grp = blockIdx.x >> 4;
    const int j0  = (blockIdx.x & 15) * COLS_PER_BLK;
    const int b0  = grp * B_PER_GROUP;
    const int kb  = w * 128;

    // Wf slice -> registers (128 floats = 64 u64)
    u64 wf2[64];
    #pragma unroll
    for (int i = 0; i < 32; i++) {
        float4 v = *(const float4*)&Whf[(j0 + j) * HDIM + kb + 4 * i];
        wf2[2*i] = pack2(v.x, v.y); wf2[2*i+1] = pack2(v.z, v.w);
    }
    // Wh slice -> private SMEM region (thread-local)
    float* wr = &whs[(w * 32 + j) * WH_STRIDE];
    #pragma unroll
    for (int i = 0; i < 32; i++)
        *(float4*)&wr[4 * i] = *(const float4*)&Whh[(j0 + j) * HDIM + kb + 4 * i];

    float hp = h0[(b0 + w) * HDIM + j0 + j];
    __syncthreads();

    unsigned int* cA = &g_cnt[grp * 16 + 0];
    unsigned int* cB = &g_cnt[grp * 16 + 8];

    float* sb = &srcs[w * 512];
    const long xstep = (long)BATCH * HDIM;
    long xoff = (long)(b0 + w) * HDIM + j0 + j;   // rolling [t,b,*] offset

    float f_reg = 0.0f;

    for (int t = 0; t < T_STEPS; t++) {
        const unsigned int tgt = (unsigned int)(t + 1) * 64u;
        const float xf_v = __ldcs(&g_xf[xoff]);
        const float xh_v = __ldcs(&g_xh[xoff]);

        // ---- wait for h_{t-1}: lane 0 polls, syncwarp broadcasts ----
        if (t > 0) {
            if (j == 0) while (ld_acq(cB) < tgt - 64u) { }
            __syncwarp();
        }

        // ---- per-warp gather: 4 rows x own k-slice of h ----
        {
            const float4* hb = (const float4*)&g_hbuf[b0 * HDIM + kb];
            float4 v0 = ldcg4(hb + j);
            float4 v1 = ldcg4(hb + 128 + j);
            float4 v2 = ldcg4(hb + 256 + j);
            float4 v3 = ldcg4(hb + 384 + j);
            *(float4*)&sb[        4 * j] = v0;
            *(float4*)&sb[128 +   4 * j] = v1;
            *(float4*)&sb[256 +   4 * j] = v2;
            *(float4*)&sb[384 +   4 * j] = v3;
        }
        __syncwarp();

        // ---- GEMM A (f gate), Wf from registers ----
        {
            u64 a0 = 0ull, a1 = 0ull, a2 = 0ull, a3 = 0ull;
            #pragma unroll
            for (int i = 0; i < 32; i++) {
                u64 wlo = wf2[2*i], whi = wf2[2*i+1];
                float4 x0 = *(const float4*)&sb[        4 * i];
                float4 x1 = *(const float4*)&sb[128 +   4 * i];
                float4 x2 = *(const float4*)&sb[256 +   4 * i];
                float4 x3 = *(const float4*)&sb[384 +   4 * i];
                a0 = ffma2(wlo, pack2(x0.x, x0.y), a0);
                a0 = ffma2(whi, pack2(x0.z, x0.w), a0);
                a1 = ffma2(wlo, pack2(x1.x, x1.y), a1);
                a1 = ffma2(whi, pack2(x1.z, x1.w), a1);
                a2 = ffma2(wlo, pack2(x2.x, x2.y), a2);
                a2 = ffma2(whi, pack2(x2.z, x2.w), a2);
                a3 = ffma2(wlo, pack2(x3.x, x3.y), a3);
                a3 = ffma2(whi, pack2(x3.z, x3.w), a3);
            }
            float2 r0 = unpack2(a0), r1 = unpack2(a1);
            float2 r2 = unpack2(a2), r3 = unpack2(a3);
            partA[(0 * 4 + w) * 32 + j] = r0.x + r0.y;
            partA[(1 * 4 + w) * 32 + j] = r1.x + r1.y;
            partA[(2 * 4 + w) * 32 + j] = r2.x + r2.y;
            partA[(3 * 4 + w) * 32 + j] = r3.x + r3.y;
        }
        __syncthreads();

        // ---- finalize A: warp w owns row w ----
        {
            float s = xf_v;
            #pragma unroll
            for (int q = 0; q < 4; q++) s += partA[(w * 4 + q) * 32 + j];
            f_reg = sigmoid_f(s);
            g_gbuf[(b0 + w) * HDIM + j0 + j] = f_reg * hp;
        }
        __syncwarp();
        if (j == 0) red_release(cA);

        // ---- wait for g_t ----
        if (j == 0) while (ld_acq(cA) < tgt) { }
        __syncwarp();

        // ---- per-warp gather of g ----
        {
            const float4* gb = (const float4*)&g_gbuf[b0 * HDIM + kb];
            float4 v0 = ldcg4(gb + j);
            float4 v1 = ldcg4(gb + 128 + j);
            float4 v2 = ldcg4(gb + 256 + j);
            float4 v3 = ldcg4(gb + 384 + j);
            *(float4*)&sb[        4 * j] = v0;
            *(float4*)&sb[128 +   4 * j] = v1;
            *(float4*)&sb[256 +   4 * j] = v2;
            *(float4*)&sb[384 +   4 * j] = v3;
        }
        __syncwarp();

        // ---- GEMM B (candidate), Wh from SMEM ----
        {
            u64 a0 = 0ull, a1 = 0ull, a2 = 0ull, a3 = 0ull;
            #pragma unroll
            for (int i = 0; i < 32; i++) {
                float4 wv = *(const float4*)&wr[4 * i];
                u64 wlo = pack2(wv.x, wv.y), whi = pack2(wv.z, wv.w);
                float4 x0 = *(const float4*)&sb[        4 * i];
                float4 x1 = *(const float4*)&sb[128 +   4 * i];
                float4 x2 = *(const float4*)&sb[256 +   4 * i];
                float4 x3 = *(const float4*)&sb[384 +   4 * i];
                a0 = ffma2(wlo, pack2(x0.x, x0.y), a0);
                a0 = ffma2(whi, pack2(x0.z, x0.w), a0);
                a1 = ffma2(wlo, pack2(x1.x, x1.y), a1);
                a1 = ffma2(whi, pack2(x1.z, x1.w), a1);
                a2 = ffma2(wlo, pack2(x2.x, x2.y), a2);
                a2 = ffma2(whi, pack2(x2.z, x2.w), a2);
                a3 = ffma2(wlo, pack2(x3.x, x3.y), a3);
                a3 = ffma2(whi, pack2(x3.z, x3.w), a3);
            }
            float2 r0 = unpack2(a0), r1 = unpack2(a1);
            float2 r2 = unpack2(a2), r3 = unpack2(a3);
            partB[(0 * 4 + w) * 32 + j] = r0.x + r0.y;
            partB[(1 * 4 + w) * 32 + j] = r1.x + r1.y;
            partB[(2 * 4 + w) * 32 + j] = r2.x + r2.y;
            partB[(3 * 4 + w) * 32 + j] = r3.x + r3.y;
        }
        __syncthreads();

        // ---- finalize B: blend, emit y and h ----
        {
            float s = xh_v;
            #pragma unroll
            for (int q = 0; q < 4; q++) s += partB[(w * 4 + q) * 32 + j];
            float ht = tanh_ap(s);
            float hn = fmaf(f_reg, ht - hp, hp);        // (1-f)h + f*ht
            __stcs(&out[xoff], hn);                     // xoff == [t,b,col]
            g_hbuf[(b0 + w) * HDIM + j0 + j] = hn;
            if (t == T_STEPS - 1)
                out[(long)T_STEPS * xstep + (b0 + w) * HDIM + j0 + j] = hn;
            hp = hn;
        }
        __syncwarp();
        if (j == 0) red_release(cB);

        xoff += xstep;
    }
}

// ============================================================================
extern "C" void kernel_launch(void* const* d_in, const int* in_sizes, int n_in,
                              void* d_out, int out_size)
{
    const float* x   = (const float*)d_in[0];
    const float* h0  = (const float*)d_in[1];
    const float* Wxf = (const float*)d_in[2];
    const float* Whf = (const float*)d_in[3];
    const float* bf  = (const float*)d_in[4];
    const float* Wxh = (const float*)d_in[5];
    const float* Whh = (const float*)d_in[6];
    const float* bh  = (const float*)d_in[7];
    float* out = (float*)d_out;

    cudaFuncSetAttribute(scan_kernel,
                         cudaFuncAttributeMaxDynamicSharedMemorySize, SCAN_SMEM);

    dim3 pgrid((T_STEPS * BATCH) / 128, HDIM / 64, 2);
    proj_kernel<<<pgrid, 256>>>(x, h0, Wxf, bf, Wxh, bh);

    scan_kernel<<<N_GROUPS * BLKS_PER_GROUP, 128, SCAN_SMEM>>>(h0, Whf, Whh, out);
}